// round 5
// baseline (speedup 1.0000x reference)
#include <cuda_runtime.h>
#include <cuda_bf16.h>

// Problem constants
#define BB   64
#define TT   512
#define DIN  1024
#define UN   1024

// ---------------------------------------------------------------------------
// Phase 1: projection GEMM  xk[b,t,:] = x[b,t,:] @ W   written straight into
// d_out (the recurrence then updates d_out in place).
// Classic 128x128x8 smem-tiled fp32 SGEMM, 256 threads, 8x8 microtile.
// ---------------------------------------------------------------------------
__global__ __launch_bounds__(256, 2) void proj_kernel(const float* __restrict__ A,
                                                      const float* __restrict__ W,
                                                      float* __restrict__ C) {
    __shared__ float As[8][128];
    __shared__ float Bs[8][128];
    const int tid  = threadIdx.x;
    const int bm   = blockIdx.y * 128;
    const int bn   = blockIdx.x * 128;
    const int arow = tid >> 1;
    const int acol = (tid & 1) << 2;
    const int brow = tid >> 5;
    const int bcol = (tid & 31) << 2;
    const int ty   = tid >> 4;
    const int tx   = tid & 15;

    const float* Aptr = A + (size_t)(bm + arow) * DIN + acol;
    const float* Bptr = W + (size_t)brow * UN + bn + bcol;

    float acc[8][8];
#pragma unroll
    for (int i = 0; i < 8; i++)
#pragma unroll
        for (int j = 0; j < 8; j++) acc[i][j] = 0.f;

    for (int k0 = 0; k0 < DIN; k0 += 8) {
        float4 av = *(const float4*)(Aptr + k0);
        float4 bv = *(const float4*)(Bptr + (size_t)k0 * UN);
        As[acol + 0][arow] = av.x;
        As[acol + 1][arow] = av.y;
        As[acol + 2][arow] = av.z;
        As[acol + 3][arow] = av.w;
        *(float4*)&Bs[brow][bcol] = bv;
        __syncthreads();
#pragma unroll
        for (int k = 0; k < 8; k++) {
            float a[8], b[8];
            *(float4*)(a)     = *(const float4*)&As[k][ty * 8];
            *(float4*)(a + 4) = *(const float4*)&As[k][ty * 8 + 4];
            *(float4*)(b)     = *(const float4*)&Bs[k][tx * 8];
            *(float4*)(b + 4) = *(const float4*)&Bs[k][tx * 8 + 4];
#pragma unroll
            for (int i = 0; i < 8; i++)
#pragma unroll
                for (int j = 0; j < 8; j++)
                    acc[i][j] = fmaf(a[i], b[j], acc[i][j]);
        }
        __syncthreads();
    }

    float* Cptr = C + (size_t)(bm + ty * 8) * UN + bn + tx * 8;
#pragma unroll
    for (int i = 0; i < 8; i++) {
        *(float4*)(Cptr + (size_t)i * UN) =
            make_float4(acc[i][0], acc[i][1], acc[i][2], acc[i][3]);
        *(float4*)(Cptr + (size_t)i * UN + 4) =
            make_float4(acc[i][4], acc[i][5], acc[i][6], acc[i][7]);
    }
}

// ---------------------------------------------------------------------------
// Phase 2: persistent recurrent kernel.
//   h(t) = relu(xk(t) + h(t-1) @ Ur),   updated in place in d_out.
// 128 CTAs (all co-resident on 148+ SMs), CTA tile = 16 (batch rows) x 32
// (hidden cols).  Its 1024x32 slice of Ur lives in smem for all 512 steps.
// Global sync: monotonic counter barrier (fence -> atomicAdd -> acquire-spin).
// ---------------------------------------------------------------------------
#define GR      128          // persistent grid size (<= SM count!)
#define NT      256          // threads per CTA
#define HS_PAD  1028         // h row pitch in floats (pad breaks bank aliasing)
#define SMEM_FLOATS (1024 * 32 + 16 * HS_PAD)
#define SMEM_BYTES  (SMEM_FLOATS * 4)   // 196864 B

__device__ unsigned g_bar_count;   // zero-initialized at module load

__global__ void __launch_bounds__(NT, 1) rnn_kernel(const float* __restrict__ Ur,
                                                    float* __restrict__ out) {
    extern __shared__ float smem[];
    float* Us = smem;                  // [1024][32]  weight slice, resident
    float* hs = smem + 1024 * 32;      // [16][HS_PAD] h(t-1) tile

    const int tid = threadIdx.x;
    const int mi  = blockIdx.x >> 5;   // 0..3   : batch-row tile
    const int ni  = blockIdx.x & 31;   // 0..31  : hidden-col tile
    const int n2  = tid & 15;          // column pair within tile
    const int m   = tid >> 4;          // row within tile (0..15)

    // Load this CTA's Ur slice: columns [ni*32, ni*32+32), all 1024 k-rows.
    {
        const float* up = Ur + ni * 32;
        for (int idx = tid; idx < 1024 * 8; idx += NT) {   // 8 float4 per row
            int k = idx >> 3;
            int c = (idx & 7) << 2;
            float4 v = *(const float4*)(up + (size_t)k * UN + c);
            *(float4*)&Us[k * 32 + c] = v;
        }
    }

    // ---- step 0: h(0) = relu(xk(0)) (h(-1) == 0) ----
    {
        float* o = out + ((size_t)(mi * 16 + m) * TT + 0) * UN + ni * 32 + n2 * 2;
        float2 xv = __ldcg((const float2*)o);
        xv.x = fmaxf(xv.x, 0.f);
        xv.y = fmaxf(xv.y, 0.f);
        *(float2*)o = xv;
    }

    unsigned target = GR;
    // barrier after step 0
    __threadfence();
    __syncthreads();
    if (tid == 0) {
        atomicAdd(&g_bar_count, 1);
        unsigned v;
        do {
            asm volatile("ld.global.acquire.gpu.u32 %0, [%1];" : "=r"(v) : "l"(&g_bar_count));
        } while (v < target);
    }
    __syncthreads();

    for (int t = 1; t < TT; ++t) {
        // Load h(t-1) tile (16 rows x 1024) from global (L2 is coherence pt).
        for (int idx = tid; idx < 16 * 256; idx += NT) {   // 4096 float4
            int r = idx >> 8;
            int c = (idx & 255) << 2;
            float4 v = __ldcg((const float4*)(out +
                        ((size_t)(mi * 16 + r) * TT + (t - 1)) * UN + c));
            *(float4*)&hs[r * HS_PAD + c] = v;
        }
        __syncthreads();

        float c0 = 0.f, c1 = 0.f;
        const float* hrow = hs + m * HS_PAD;
        const float* ucol = Us + n2 * 2;
#pragma unroll 4
        for (int k4 = 0; k4 < 256; ++k4) {
            float4 hv = *(const float4*)(hrow + k4 * 4);
            float2 u0 = *(const float2*)(ucol + (k4 * 4 + 0) * 32);
            float2 u1 = *(const float2*)(ucol + (k4 * 4 + 1) * 32);
            float2 u2 = *(const float2*)(ucol + (k4 * 4 + 2) * 32);
            float2 u3 = *(const float2*)(ucol + (k4 * 4 + 3) * 32);
            c0 = fmaf(hv.x, u0.x, c0); c1 = fmaf(hv.x, u0.y, c1);
            c0 = fmaf(hv.y, u1.x, c0); c1 = fmaf(hv.y, u1.y, c1);
            c0 = fmaf(hv.z, u2.x, c0); c1 = fmaf(hv.z, u2.y, c1);
            c0 = fmaf(hv.w, u3.x, c0); c1 = fmaf(hv.w, u3.y, c1);
        }

        // epilogue: out[.,t,.] = relu(xk + h@Ur)   (in place)
        {
            float* o = out + ((size_t)(mi * 16 + m) * TT + t) * UN + ni * 32 + n2 * 2;
            float2 xv = __ldcg((const float2*)o);
            float2 r;
            r.x = fmaxf(xv.x + c0, 0.f);
            r.y = fmaxf(xv.y + c1, 0.f);
            *(float2*)o = r;
        }

        if (t < TT - 1) {
            target += GR;
            __threadfence();     // make this thread's store visible gpu-wide
            __syncthreads();     // also protects hs before next step's refill
            if (tid == 0) {
                atomicAdd(&g_bar_count, 1);
                unsigned v;
                do {
                    asm volatile("ld.global.acquire.gpu.u32 %0, [%1];" : "=r"(v) : "l"(&g_bar_count));
                } while (v < target);
            }
            __syncthreads();
        }
    }
}

// Runs after the persistent kernel (stream-ordered) so every graph replay
// starts with a zeroed barrier counter. First call relies on static zero-init.
__global__ void reset_bar_kernel() { g_bar_count = 0; }

// ---------------------------------------------------------------------------
extern "C" void kernel_launch(void* const* d_in, const int* in_sizes, int n_in,
                              void* d_out, int out_size) {
    const float* x  = (const float*)d_in[0];   // [64,512,1024]
    const float* W  = (const float*)d_in[1];   // [1024,1024]
    const float* Ur = (const float*)d_in[2];   // [1024,1024]
    float* out = (float*)d_out;                // [64,512,1024]

    cudaFuncSetAttribute(rnn_kernel, cudaFuncAttributeMaxDynamicSharedMemorySize,
                         SMEM_BYTES);

    dim3 pgrid(UN / 128, (BB * TT) / 128);     // (8, 256)
    proj_kernel<<<pgrid, 256>>>(x, W, out);
    rnn_kernel<<<GR, NT, SMEM_BYTES>>>(Ur, out);
    reset_bar_kernel<<<1, 1>>>();
}

// round 7
// speedup vs baseline: 1.1267x; 1.1267x over previous
#include <cuda_runtime.h>
#include <cuda_bf16.h>
#include <cstdint>

// Problem constants
#define BB   64
#define TT   512
#define DIN  1024
#define UN   1024

// ---------------------------------------------------------------------------
// Scratch: bf16 hi/lo split of x, and of W transposed (K-major B operand).
// ---------------------------------------------------------------------------
__device__ __align__(128) __nv_bfloat16 g_xhi[(size_t)BB * TT * DIN];
__device__ __align__(128) __nv_bfloat16 g_xlo[(size_t)BB * TT * DIN];
__device__ __align__(128) __nv_bfloat16 g_whi[(size_t)UN * DIN];   // [n][k]
__device__ __align__(128) __nv_bfloat16 g_wlo[(size_t)UN * DIN];   // [n][k]

__global__ void split_x_kernel(const float* __restrict__ x) {
    size_t i = ((size_t)blockIdx.x * blockDim.x + threadIdx.x) * 4;
    const size_t n = (size_t)BB * TT * DIN;
    if (i >= n) return;
    float4 v = *(const float4*)(x + i);
    __nv_bfloat16 h0 = __float2bfloat16(v.x);
    __nv_bfloat16 h1 = __float2bfloat16(v.y);
    __nv_bfloat16 h2 = __float2bfloat16(v.z);
    __nv_bfloat16 h3 = __float2bfloat16(v.w);
    *(__nv_bfloat162*)(g_xhi + i)     = __halves2bfloat162(h0, h1);
    *(__nv_bfloat162*)(g_xhi + i + 2) = __halves2bfloat162(h2, h3);
    *(__nv_bfloat162*)(g_xlo + i) = __halves2bfloat162(
        __float2bfloat16(v.x - __bfloat162float(h0)),
        __float2bfloat16(v.y - __bfloat162float(h1)));
    *(__nv_bfloat162*)(g_xlo + i + 2) = __halves2bfloat162(
        __float2bfloat16(v.z - __bfloat162float(h2)),
        __float2bfloat16(v.w - __bfloat162float(h3)));
}

// split + transpose W: W[k][n] -> g_whi/g_wlo [n][k]
__global__ void split_w_kernel(const float* __restrict__ W) {
    size_t i = (size_t)blockIdx.x * blockDim.x + threadIdx.x;
    if (i >= (size_t)DIN * UN) return;
    int k  = (int)(i / UN);
    int nn = (int)(i % UN);
    float v = W[i];
    __nv_bfloat16 h = __float2bfloat16(v);
    g_whi[(size_t)nn * DIN + k] = h;
    g_wlo[(size_t)nn * DIN + k] = __float2bfloat16(v - __bfloat162float(h));
}

// ---------------------------------------------------------------------------
// mma.sync helpers (sm_80-era PTX -> HMMA, valid on plain sm_103 target)
// ---------------------------------------------------------------------------
__device__ __forceinline__ uint32_t smem_u32(const void* p) {
    uint32_t a;
    asm("{ .reg .u64 t; cvta.to.shared.u64 t, %1; cvt.u32.u64 %0, t; }"
        : "=r"(a) : "l"(p));
    return a;
}

__device__ __forceinline__ void ldsm4(uint32_t* r, uint32_t addr) {
    asm volatile(
        "ldmatrix.sync.aligned.m8n8.x4.shared.b16 {%0,%1,%2,%3}, [%4];"
        : "=r"(r[0]), "=r"(r[1]), "=r"(r[2]), "=r"(r[3]) : "r"(addr));
}

__device__ __forceinline__ void mma16816(float* c, const uint32_t* a,
                                         uint32_t b0, uint32_t b1) {
    asm volatile(
        "mma.sync.aligned.m16n8k16.row.col.f32.bf16.bf16.f32 "
        "{%0,%1,%2,%3}, {%4,%5,%6,%7}, {%8,%9}, {%0,%1,%2,%3};"
        : "+f"(c[0]), "+f"(c[1]), "+f"(c[2]), "+f"(c[3])
        : "r"(a[0]), "r"(a[1]), "r"(a[2]), "r"(a[3]), "r"(b0), "r"(b1));
}

// ---------------------------------------------------------------------------
// Projection GEMM on HMMA tensor cores:
//   out[m,n] = sum_k (xhi+xlo)[m,k]*(whi+wlo)[n,k]   (3 products, lo*lo dropped)
// CTA tile 128x128, 256 threads (warp grid 4m x 2n -> 32x64/warp), K-chunk 32.
// ---------------------------------------------------------------------------
#define PKC     32                  // k per smem chunk
#define PSTR    40                  // smem row pitch in bf16 (80B, 16B-aligned)

__global__ void __launch_bounds__(256)
proj_mma_kernel(float* __restrict__ out) {
    __shared__ __align__(128) __nv_bfloat16 sAhi[128 * PSTR];
    __shared__ __align__(128) __nv_bfloat16 sAlo[128 * PSTR];
    __shared__ __align__(128) __nv_bfloat16 sBhi[128 * PSTR];
    __shared__ __align__(128) __nv_bfloat16 sBlo[128 * PSTR];

    const int tid  = threadIdx.x;
    const int lane = tid & 31;
    const int wid  = tid >> 5;
    const int wm   = wid >> 1;          // 0..3
    const int wn   = wid & 1;           // 0..1
    const int mb   = wm * 32;
    const int nb   = wn * 64;
    const int n0   = blockIdx.x * 128;
    const int m0   = blockIdx.y * 128;

    // per-thread global/smem load coords: 512 uint4 per 128x32 tile
    int row[2], c4[2];
#pragma unroll
    for (int i = 0; i < 2; i++) {
        int idx = tid + i * 256;
        row[i] = idx >> 2;
        c4[i]  = idx & 3;
    }
    const __nv_bfloat16* gAhi = g_xhi + (size_t)m0 * DIN;
    const __nv_bfloat16* gAlo = g_xlo + (size_t)m0 * DIN;
    const __nv_bfloat16* gBhi = g_whi + (size_t)n0 * DIN;
    const __nv_bfloat16* gBlo = g_wlo + (size_t)n0 * DIN;

    float acc[2][8][4];
#pragma unroll
    for (int mt = 0; mt < 2; mt++)
#pragma unroll
        for (int nt = 0; nt < 8; nt++)
#pragma unroll
            for (int j = 0; j < 4; j++) acc[mt][nt][j] = 0.f;

    // ldmatrix base addresses (lane-dependent)
    const int lrow = lane & 15;
    const int lkb  = (lane >> 4) * 8;
    const uint32_t aAhi = smem_u32(sAhi) + ((mb + lrow) * PSTR + lkb) * 2;
    const uint32_t aAlo = smem_u32(sAlo) + ((mb + lrow) * PSTR + lkb) * 2;
    const uint32_t aBhi = smem_u32(sBhi) + ((nb + lrow) * PSTR + lkb) * 2;
    const uint32_t aBlo = smem_u32(sBlo) + ((nb + lrow) * PSTR + lkb) * 2;

    uint4 pf[4][2];
    // prefetch chunk 0
#pragma unroll
    for (int i = 0; i < 2; i++) {
        size_t off = (size_t)row[i] * DIN + c4[i] * 8;
        pf[0][i] = *(const uint4*)(gAhi + off);
        pf[1][i] = *(const uint4*)(gAlo + off);
        pf[2][i] = *(const uint4*)(gBhi + off);
        pf[3][i] = *(const uint4*)(gBlo + off);
    }

    for (int kc = 0; kc < DIN / PKC; ++kc) {
        // commit prefetched chunk to smem
#pragma unroll
        for (int i = 0; i < 2; i++) {
            int so = row[i] * PSTR + c4[i] * 8;
            *(uint4*)(sAhi + so) = pf[0][i];
            *(uint4*)(sAlo + so) = pf[1][i];
            *(uint4*)(sBhi + so) = pf[2][i];
            *(uint4*)(sBlo + so) = pf[3][i];
        }
        __syncthreads();

        if (kc + 1 < DIN / PKC) {
            const int k0n = (kc + 1) * PKC;
#pragma unroll
            for (int i = 0; i < 2; i++) {
                size_t off = (size_t)row[i] * DIN + k0n + c4[i] * 8;
                pf[0][i] = *(const uint4*)(gAhi + off);
                pf[1][i] = *(const uint4*)(gAlo + off);
                pf[2][i] = *(const uint4*)(gBhi + off);
                pf[3][i] = *(const uint4*)(gBlo + off);
            }
        }

#pragma unroll
        for (int ks = 0; ks < 2; ++ks) {
            const uint32_t ko = ks * 32;   // 16 bf16 = 32 bytes
            uint32_t ahi[2][4], alo[2][4];
#pragma unroll
            for (int mt = 0; mt < 2; mt++) {
                ldsm4(ahi[mt], aAhi + mt * (16 * PSTR * 2) + ko);
                ldsm4(alo[mt], aAlo + mt * (16 * PSTR * 2) + ko);
            }
            uint32_t bhi[4][4], blo[4][4];
#pragma unroll
            for (int p = 0; p < 4; p++) {
                ldsm4(bhi[p], aBhi + p * (16 * PSTR * 2) + ko);
                ldsm4(blo[p], aBlo + p * (16 * PSTR * 2) + ko);
            }
#pragma unroll
            for (int mt = 0; mt < 2; mt++) {
#pragma unroll
                for (int nt = 0; nt < 8; nt++) {
                    const int p   = nt >> 1;
                    const int sel = nt & 1;
                    const uint32_t bh0 = bhi[p][sel], bh1 = bhi[p][sel + 2];
                    const uint32_t bl0 = blo[p][sel], bl1 = blo[p][sel + 2];
                    mma16816(acc[mt][nt], ahi[mt], bh0, bh1);
                    mma16816(acc[mt][nt], ahi[mt], bl0, bl1);
                    mma16816(acc[mt][nt], alo[mt], bh0, bh1);
                }
            }
        }
        __syncthreads();
    }

    // epilogue: fragment -> float2 stores
    const int erow = lane >> 2;
    const int ecol = (lane & 3) * 2;
#pragma unroll
    for (int mt = 0; mt < 2; mt++) {
#pragma unroll
        for (int nt = 0; nt < 8; nt++) {
            const int m = m0 + mb + mt * 16 + erow;
            const int n = n0 + nb + nt * 8 + ecol;
            float2 v0 = make_float2(acc[mt][nt][0], acc[mt][nt][1]);
            float2 v1 = make_float2(acc[mt][nt][2], acc[mt][nt][3]);
            *(float2*)(out + (size_t)m * UN + n)       = v0;
            *(float2*)(out + (size_t)(m + 8) * UN + n) = v1;
        }
    }
}

// ---------------------------------------------------------------------------
// Phase 2: persistent recurrent kernel (unchanged from passing R5 kernel).
//   h(t) = relu(xk(t) + h(t-1) @ Ur),  in place in d_out.
// ---------------------------------------------------------------------------
#define GR      128
#define NT      256
#define HS_PAD  1028
#define SMEM_FLOATS (1024 * 32 + 16 * HS_PAD)
#define SMEM_BYTES  (SMEM_FLOATS * 4)

__device__ unsigned g_bar_count;

__global__ void __launch_bounds__(NT, 1) rnn_kernel(const float* __restrict__ Ur,
                                                    float* __restrict__ out) {
    extern __shared__ float smemf[];
    float* Us = smemf;
    float* hs = smemf + 1024 * 32;

    const int tid = threadIdx.x;
    const int mi  = blockIdx.x >> 5;
    const int ni  = blockIdx.x & 31;
    const int n2  = tid & 15;
    const int m   = tid >> 4;

    {
        const float* up = Ur + ni * 32;
        for (int idx = tid; idx < 1024 * 8; idx += NT) {
            int k = idx >> 3;
            int c = (idx & 7) << 2;
            float4 v = *(const float4*)(up + (size_t)k * UN + c);
            *(float4*)&Us[k * 32 + c] = v;
        }
    }

    {
        float* o = out + ((size_t)(mi * 16 + m) * TT + 0) * UN + ni * 32 + n2 * 2;
        float2 xv = __ldcg((const float2*)o);
        xv.x = fmaxf(xv.x, 0.f);
        xv.y = fmaxf(xv.y, 0.f);
        *(float2*)o = xv;
    }

    unsigned target = GR;
    __threadfence();
    __syncthreads();
    if (tid == 0) {
        atomicAdd(&g_bar_count, 1);
        unsigned v;
        do {
            asm volatile("ld.global.acquire.gpu.u32 %0, [%1];" : "=r"(v) : "l"(&g_bar_count));
        } while (v < target);
    }
    __syncthreads();

    for (int t = 1; t < TT; ++t) {
        for (int idx = tid; idx < 16 * 256; idx += NT) {
            int r = idx >> 8;
            int c = (idx & 255) << 2;
            float4 v = __ldcg((const float4*)(out +
                        ((size_t)(mi * 16 + r) * TT + (t - 1)) * UN + c));
            *(float4*)&hs[r * HS_PAD + c] = v;
        }
        __syncthreads();

        float c0 = 0.f, c1 = 0.f;
        const float* hrow = hs + m * HS_PAD;
        const float* ucol = Us + n2 * 2;
#pragma unroll 4
        for (int k4 = 0; k4 < 256; ++k4) {
            float4 hv = *(const float4*)(hrow + k4 * 4);
            float2 u0 = *(const float2*)(ucol + (k4 * 4 + 0) * 32);
            float2 u1 = *(const float2*)(ucol + (k4 * 4 + 1) * 32);
            float2 u2 = *(const float2*)(ucol + (k4 * 4 + 2) * 32);
            float2 u3 = *(const float2*)(ucol + (k4 * 4 + 3) * 32);
            c0 = fmaf(hv.x, u0.x, c0); c1 = fmaf(hv.x, u0.y, c1);
            c0 = fmaf(hv.y, u1.x, c0); c1 = fmaf(hv.y, u1.y, c1);
            c0 = fmaf(hv.z, u2.x, c0); c1 = fmaf(hv.z, u2.y, c1);
            c0 = fmaf(hv.w, u3.x, c0); c1 = fmaf(hv.w, u3.y, c1);
        }

        {
            float* o = out + ((size_t)(mi * 16 + m) * TT + t) * UN + ni * 32 + n2 * 2;
            float2 xv = __ldcg((const float2*)o);
            float2 r;
            r.x = fmaxf(xv.x + c0, 0.f);
            r.y = fmaxf(xv.y + c1, 0.f);
            *(float2*)o = r;
        }

        if (t < TT - 1) {
            target += GR;
            __threadfence();
            __syncthreads();
            if (tid == 0) {
                atomicAdd(&g_bar_count, 1);
                unsigned v;
                do {
                    asm volatile("ld.global.acquire.gpu.u32 %0, [%1];" : "=r"(v) : "l"(&g_bar_count));
                } while (v < target);
            }
            __syncthreads();
        }
    }
}

__global__ void reset_bar_kernel() { g_bar_count = 0; }

// ---------------------------------------------------------------------------
extern "C" void kernel_launch(void* const* d_in, const int* in_sizes, int n_in,
                              void* d_out, int out_size) {
    const float* x  = (const float*)d_in[0];   // [64,512,1024]
    const float* W  = (const float*)d_in[1];   // [1024,1024]
    const float* Ur = (const float*)d_in[2];   // [1024,1024]
    float* out = (float*)d_out;                // [64,512,1024]

    cudaFuncSetAttribute(rnn_kernel, cudaFuncAttributeMaxDynamicSharedMemorySize,
                         SMEM_BYTES);

    // split/transpose pre-pass
    {
        size_t nx = (size_t)BB * TT * DIN / 4;
        split_x_kernel<<<(unsigned)((nx + 255) / 256), 256>>>(x);
        size_t nw = (size_t)DIN * UN;
        split_w_kernel<<<(unsigned)((nw + 255) / 256), 256>>>(W);
    }

    // tensor-core (HMMA) projection straight into d_out
    dim3 pgrid(UN / 128, (BB * TT) / 128);     // (8, 256)
    proj_mma_kernel<<<pgrid, 256>>>(out);

    // fp32 persistent recurrence (in place), then barrier reset for replay
    rnn_kernel<<<GR, NT, SMEM_BYTES>>>(Ur, out);
    reset_bar_kernel<<<1, 1>>>();
}